// round 12
// baseline (speedup 1.0000x reference)
#include <cuda_runtime.h>
#include <cuda_fp16.h>
#include <cstdint>

#define C        384
#define NQKV     1152
#define NWIN     2048   // 32 images * 64 windows
#define D        64     // tokens per window
#define KCH      32     // K per pipeline chunk
#define NCHUNK   (C / KCH)   // 12
#define NSTAGE   3

// GEMM stage layout (fp16): A[256][32] (16KB) + B[128][32] (8KB)
#define SA    0
#define SB    16384
#define STAGE_STRIDE 24576
#define SMEM_BYTES 135168          // epilogue S[256][132]*4; > 3*24576

// ---------------------------------------------------------------------------
// Scratch (device globals are the sanctioned scratch mechanism).
__device__ __half g_x_h [(size_t)32 * 64 * 64 * C];   // fp16 activations
__device__ __half g_qkv [(size_t)NWIN * D * NQKV];    // fp16 qkv
__device__ __half g_ctx [(size_t)NWIN * D * C];       // fp16 attn output
__device__ __half g_wqkv[(size_t)NQKV * C];           // W^T [n][k] fp16
__device__ __half g_wout[(size_t)C * C];

// ---------------------------------------------------------------------------
__device__ __forceinline__ uint32_t smem_u32(const void* p) {
    uint32_t a;
    asm("{ .reg .u64 t; cvta.to.shared.u64 t, %1; cvt.u32.u64 %0, t; }"
        : "=r"(a) : "l"(p));
    return a;
}
__device__ __forceinline__ void cp16(uint32_t d, const void* s) {
    asm volatile("cp.async.ca.shared.global [%0], [%1], 16;" :: "r"(d), "l"(s));
}
#define CP_COMMIT() asm volatile("cp.async.commit_group;" ::: "memory")
#define CP_WAIT0()  asm volatile("cp.async.wait_group 0;" ::: "memory")
#define CP_WAIT1()  asm volatile("cp.async.wait_group 1;" ::: "memory")
#define CP_WAIT2()  asm volatile("cp.async.wait_group 2;" ::: "memory")

__device__ __forceinline__ void ldsm4(uint32_t r[4], uint32_t addr) {
    asm volatile("ldmatrix.sync.aligned.m8n8.x4.shared.b16 {%0,%1,%2,%3}, [%4];"
                 : "=r"(r[0]), "=r"(r[1]), "=r"(r[2]), "=r"(r[3]) : "r"(addr));
}
__device__ __forceinline__ void ldsm4t(uint32_t r[4], uint32_t addr) {
    asm volatile("ldmatrix.sync.aligned.m8n8.x4.trans.shared.b16 {%0,%1,%2,%3}, [%4];"
                 : "=r"(r[0]), "=r"(r[1]), "=r"(r[2]), "=r"(r[3]) : "r"(addr));
}
__device__ __forceinline__ void mma_f16(float d[4], const uint32_t a[4],
                                        const uint32_t b[2]) {
    asm volatile(
        "mma.sync.aligned.m16n8k16.row.col.f32.f16.f16.f32 "
        "{%0,%1,%2,%3}, {%4,%5,%6,%7}, {%8,%9}, {%0,%1,%2,%3};"
        : "+f"(d[0]), "+f"(d[1]), "+f"(d[2]), "+f"(d[3])
        : "r"(a[0]), "r"(a[1]), "r"(a[2]), "r"(a[3]), "r"(b[0]), "r"(b[1]));
}
// 64-byte-row swizzle: granule col ^= (row>>1)&3  (conflict-free for ldsm/STS/cp)
__device__ __forceinline__ uint32_t sw64(int row, int cg) {
    return (uint32_t)(row * 64 + ((cg ^ ((row >> 1) & 3)) << 4));
}

// ---------------------------------------------------------------------------
// Prep kernels: fp16 conversion (+ transpose for weights).
// ---------------------------------------------------------------------------
__global__ void prep_x(const float* __restrict__ x) {
    size_t i4 = ((size_t)blockIdx.x * 256 + threadIdx.x) * 4;
    float4 v = *(const float4*)(x + i4);
    __half2 a = make_half2(__float2half_rn(v.x), __float2half_rn(v.y));
    __half2 b = make_half2(__float2half_rn(v.z), __float2half_rn(v.w));
    *(uint2*)&g_x_h[i4] = make_uint2(*(uint32_t*)&a, *(uint32_t*)&b);
}
__global__ void prep_wqkv(const float* __restrict__ w) {
    int lin = blockIdx.x * 256 + threadIdx.x;
    int k4 = (lin % 96) * 4;
    int n  = lin / 96;
    __half2 a = make_half2(__float2half_rn(w[(size_t)(k4 + 0) * NQKV + n]),
                           __float2half_rn(w[(size_t)(k4 + 1) * NQKV + n]));
    __half2 b = make_half2(__float2half_rn(w[(size_t)(k4 + 2) * NQKV + n]),
                           __float2half_rn(w[(size_t)(k4 + 3) * NQKV + n]));
    *(uint2*)&g_wqkv[(size_t)n * C + k4] = make_uint2(*(uint32_t*)&a, *(uint32_t*)&b);
}
__global__ void prep_wout(const float* __restrict__ w) {
    int lin = blockIdx.x * 256 + threadIdx.x;
    int k4 = (lin % 96) * 4;
    int n  = lin / 96;
    __half2 a = make_half2(__float2half_rn(w[(size_t)(k4 + 0) * C + n]),
                           __float2half_rn(w[(size_t)(k4 + 1) * C + n]));
    __half2 b = make_half2(__float2half_rn(w[(size_t)(k4 + 2) * C + n]),
                           __float2half_rn(w[(size_t)(k4 + 3) * C + n]));
    *(uint2*)&g_wout[(size_t)n * C + k4] = make_uint2(*(uint32_t*)&a, *(uint32_t*)&b);
}

// Gathered token index (roll -4 + window partition); row 0..255 of a 4-window CTA.
__device__ __forceinline__ size_t qkv_row_off(int wquad, int row) {
    int win = wquad * 4 + (row >> 6);
    int img = win >> 6, wi = win & 63, wr = wi >> 3, wc = wi & 7;
    int t = row & 63, ri = t >> 3, ci = t & 7;
    int gr = (wr * 8 + ri + 4) & 63;
    int gc = (wc * 8 + ci + 4) & 63;
    return (((size_t)img * 64 + gr) * 64 + gc) * C;
}

// ---------------------------------------------------------------------------
// mma on one staged chunk (KCH=32): fp16 single pass. 16 warps, 256x128 acc.
// ---------------------------------------------------------------------------
__device__ __forceinline__ void mma_stage(uint32_t sbase, int lane, int wm, int wn,
                                          float acc[4][4][4])
{
    const int aro = (lane & 7) + ((lane >> 3) & 1) * 8;
    const int cgs = lane >> 4;
#pragma unroll
    for (int ks = 0; ks < 2; ++ks) {
        const int cg = ks * 2 + cgs;
        uint32_t bh[4][2];
#pragma unroll
        for (int np = 0; np < 2; ++np) {
            int r = wn + np * 16 + aro;
            uint32_t t[4];
            ldsm4(t, sbase + SB + sw64(r, cg));
            bh[np*2][0] = t[0]; bh[np*2+1][0] = t[1];
            bh[np*2][1] = t[2]; bh[np*2+1][1] = t[3];
        }
        uint32_t a[4][4];
#pragma unroll
        for (int mi = 0; mi < 4; ++mi)
            ldsm4(a[mi], sbase + SA + sw64(wm + mi * 16 + aro, cg));
#pragma unroll
        for (int mi = 0; mi < 4; ++mi)
#pragma unroll
            for (int ni = 0; ni < 4; ++ni)
                mma_f16(acc[mi][ni], a[mi], bh[ni]);
    }
}

__device__ __forceinline__ void acc_to_smem(float (*S)[132], int tid,
                                            float acc[4][4][4])
{
    const int lane = tid & 31, wid = tid >> 5;
    const int wm = (wid & 3) * 64;
    const int wn = (wid >> 2) * 32;
    const int er = lane >> 2, ec = (lane & 3) * 2;
#pragma unroll
    for (int mi = 0; mi < 4; ++mi)
#pragma unroll
        for (int ni = 0; ni < 4; ++ni) {
            float* d = acc[mi][ni];
            *(float2*)&S[wm + mi*16 + er][wn + ni*8 + ec]     = make_float2(d[0], d[1]);
            *(float2*)&S[wm + mi*16 + 8 + er][wn + ni*8 + ec] = make_float2(d[2], d[3]);
        }
}

// Issue one chunk: per thread 2 A granules + 1 B granule.
__device__ __forceinline__ void issue_chunk(
    uint32_t s0, int k0,
    uint32_t dA0, uint32_t dA1, uint32_t dB,
    const __half* pA0, const __half* pA1, const __half* pB)
{
    cp16(s0 + SA + dA0, pA0 + k0);
    cp16(s0 + SA + dA1, pA1 + k0);
    cp16(s0 + SB + dB,  pB  + k0);
    CP_COMMIT();
}

// ---------------------------------------------------------------------------
// Kernel 1: QKV. grid = (9, 512), 512 threads. Writes g_qkv fp16.
// ---------------------------------------------------------------------------
__global__ __launch_bounds__(512, 1) void qkv_mma(const float* __restrict__ bias)
{
    extern __shared__ char smem[];
    const uint32_t sb = smem_u32(smem);
    const int tid = threadIdx.x, lane = tid & 31, wid = tid >> 5;
    const int wquad = blockIdx.y;
    const int n0 = blockIdx.x * 128;
    const int wm = (wid & 3) * 64, wn = (wid >> 2) * 32;

    const int arow = tid >> 1;
    const int cgA0 = (tid & 1) * 2;
    const uint32_t dA0 = sw64(arow, cgA0), dA1 = sw64(arow, cgA0 + 1);
    const int brow = tid >> 2;
    const int cgB  = tid & 3;
    const uint32_t dB = sw64(brow, cgB);

    const __half* pA0 = g_x_h + qkv_row_off(wquad, arow) + cgA0 * 8;
    const __half* pA1 = pA0 + 8;
    const __half* pB  = g_wqkv + (size_t)(n0 + brow) * C + cgB * 8;

    float acc[4][4][4];
#pragma unroll
    for (int mi = 0; mi < 4; ++mi)
#pragma unroll
        for (int ni = 0; ni < 4; ++ni)
#pragma unroll
            for (int q = 0; q < 4; ++q) acc[mi][ni][q] = 0.f;

    issue_chunk(sb,                0,   dA0, dA1, dB, pA0, pA1, pB);
    issue_chunk(sb + STAGE_STRIDE, KCH, dA0, dA1, dB, pA0, pA1, pB);

#pragma unroll 1
    for (int it = 0; it < NCHUNK; ++it) {
        if (it + 2 < NCHUNK)
            issue_chunk(sb + ((it + 2) % NSTAGE) * STAGE_STRIDE, (it + 2) * KCH,
                        dA0, dA1, dB, pA0, pA1, pB);
        if (it < NCHUNK - 2)      { CP_WAIT2(); }
        else if (it == NCHUNK - 2){ CP_WAIT1(); }
        else                      { CP_WAIT0(); }
        __syncthreads();
        mma_stage(sb + (it % NSTAGE) * STAGE_STRIDE, lane, wm, wn, acc);
        __syncthreads();
    }

    float (*S)[132] = (float(*)[132])smem;
    acc_to_smem(S, tid, acc);
    __syncthreads();

    const float4 bb = *(const float4*)&bias[n0 + lane * 4];
#pragma unroll
    for (int p = 0; p < 16; ++p) {
        int r = p * 16 + wid;
        float4 v = *(const float4*)&S[r][lane * 4];
        __half2 h0 = make_half2(__float2half_rn(v.x + bb.x), __float2half_rn(v.y + bb.y));
        __half2 h1 = make_half2(__float2half_rn(v.z + bb.z), __float2half_rn(v.w + bb.w));
        size_t m = (size_t)wquad * 256 + r;
        *(uint2*)&g_qkv[m * NQKV + n0 + lane * 4] =
            make_uint2(*(uint32_t*)&h0, *(uint32_t*)&h1);
    }
}

// ---------------------------------------------------------------------------
// Kernel 2: flash-style fp16 HMMA attention, 4 heads per CTA.
// grid = (2048, 3), 512 threads (16 warps: hsub = wid>>2, w = wid&3).
// Per-head smem block (12KB): Q[64][64B] K[64][64B] V[64][64B].
// ---------------------------------------------------------------------------
#define AQ 0
#define AK 4096
#define AV 8192
#define HEAD_SMEM 12288

__global__ __launch_bounds__(512) void attn_mma(const float* __restrict__ bt)
{
    __shared__ char ts[4 * HEAD_SMEM];
    __shared__ float s_bias[4][32];
    const uint32_t sb0 = smem_u32(ts);
    const int tid = threadIdx.x, lane = tid & 31, wid = tid >> 5;
    const int hsub = wid >> 2;          // 0..3: head within CTA
    const int w    = wid & 3;           // row-block within head
    const int win  = blockIdx.x;
    const int h    = blockIdx.y * 4 + hsub;
    const float scale = 0.17677669529663687f;  // 1/sqrt(32)

    // bias: warps 0..3 each load one head's table
    if (wid < 4 && lane < 29)
        s_bias[wid][lane] = bt[(lane + 15) * 12 + blockIdx.y * 4 + wid];

    const uint32_t sb = sb0 + hsub * HEAD_SMEM;

    // stage this head's q/k/v: 128 threads of the head group (tid&127)
    {
        const int wg = tid & 127;
        const int row = wg >> 1;
        const int cg0 = (wg & 1) * 2;
        const uint32_t d0 = sw64(row, cg0), d1 = sw64(row, cg0 + 1);
        size_t base = ((size_t)win * D + row) * NQKV + (size_t)h * 32 + cg0 * 8;
        const __half* p = g_qkv + base;
        cp16(sb + AQ + d0, p);        cp16(sb + AQ + d1, p + 8);
        cp16(sb + AK + d0, p + 384);  cp16(sb + AK + d1, p + 392);
        cp16(sb + AV + d0, p + 768);  cp16(sb + AV + d1, p + 776);
        CP_COMMIT();
    }
    CP_WAIT0();
    __syncthreads();

    const int aro = (lane & 7) + ((lane >> 3) & 1) * 8;
    const int cgs = lane >> 4;

    uint32_t q[2][4];
#pragma unroll
    for (int ks = 0; ks < 2; ++ks)
        ldsm4(q[ks], sb + AQ + sw64(w * 16 + aro, ks * 2 + cgs));

    float sacc[8][4];
#pragma unroll
    for (int nt = 0; nt < 8; ++nt)
#pragma unroll
        for (int qq = 0; qq < 4; ++qq) sacc[nt][qq] = 0.f;

#pragma unroll
    for (int jb = 0; jb < 4; ++jb) {
#pragma unroll
        for (int ks = 0; ks < 2; ++ks) {
            uint32_t t[4];
            ldsm4(t, sb + AK + sw64(jb * 16 + aro, ks * 2 + cgs));
            uint32_t b0[2] = {t[0], t[2]}, b1[2] = {t[1], t[3]};
            mma_f16(sacc[jb*2],   q[ks], b0);
            mma_f16(sacc[jb*2+1], q[ks], b1);
        }
    }

    const int i0 = w * 16 + (lane >> 2);
    const int i1 = i0 + 8;
    const int jc = 2 * (lane & 3);
    const int wr8 = ((win & 63) >> 3) * 8, wc8 = (win & 7) * 8;
#define SUMOF(t)  (((t) >> 3) + ((t) & 7))
#define REGOF(t)  ({ int _gr = wr8 + ((t) >> 3), _gc = wc8 + ((t) & 7); \
                     (_gr < 56 ? 0 : (_gr < 60 ? 1 : 2)) * 3 + \
                     (_gc < 56 ? 0 : (_gc < 60 ? 1 : 2)); })
    const int isum0 = SUMOF(i0), ireg0 = REGOF(i0);
    const int isum1 = SUMOF(i1), ireg1 = REGOF(i1);
    const float* bias_h = s_bias[hsub];

    float mx0 = -1e30f, mx1 = -1e30f;
#pragma unroll
    for (int nt = 0; nt < 8; ++nt) {
        int j0 = nt * 8 + jc, j1 = j0 + 1;
        int jsum0 = SUMOF(j0), jreg0 = REGOF(j0);
        int jsum1 = jsum0 + 1,  jreg1 = REGOF(j1);
        float s0 = sacc[nt][0] * scale + bias_h[isum0 - jsum0 + 14] + (ireg0 == jreg0 ? 0.f : -100.f);
        float s1 = sacc[nt][1] * scale + bias_h[isum0 - jsum1 + 14] + (ireg0 == jreg1 ? 0.f : -100.f);
        float s2 = sacc[nt][2] * scale + bias_h[isum1 - jsum0 + 14] + (ireg1 == jreg0 ? 0.f : -100.f);
        float s3 = sacc[nt][3] * scale + bias_h[isum1 - jsum1 + 14] + (ireg1 == jreg1 ? 0.f : -100.f);
        sacc[nt][0] = s0; sacc[nt][1] = s1; sacc[nt][2] = s2; sacc[nt][3] = s3;
        mx0 = fmaxf(mx0, fmaxf(s0, s1));
        mx1 = fmaxf(mx1, fmaxf(s2, s3));
    }
    mx0 = fmaxf(mx0, __shfl_xor_sync(0xffffffffu, mx0, 1));
    mx0 = fmaxf(mx0, __shfl_xor_sync(0xffffffffu, mx0, 2));
    mx1 = fmaxf(mx1, __shfl_xor_sync(0xffffffffu, mx1, 1));
    mx1 = fmaxf(mx1, __shfl_xor_sync(0xffffffffu, mx1, 2));

    float sum0 = 0.f, sum1 = 0.f;
#pragma unroll
    for (int nt = 0; nt < 8; ++nt) {
        float e0 = __expf(sacc[nt][0] - mx0);
        float e1 = __expf(sacc[nt][1] - mx0);
        float e2 = __expf(sacc[nt][2] - mx1);
        float e3 = __expf(sacc[nt][3] - mx1);
        sacc[nt][0] = e0; sacc[nt][1] = e1; sacc[nt][2] = e2; sacc[nt][3] = e3;
        sum0 += e0 + e1; sum1 += e2 + e3;
    }
    sum0 += __shfl_xor_sync(0xffffffffu, sum0, 1);
    sum0 += __shfl_xor_sync(0xffffffffu, sum0, 2);
    sum1 += __shfl_xor_sync(0xffffffffu, sum1, 1);
    sum1 += __shfl_xor_sync(0xffffffffu, sum1, 2);
    float inv0 = 1.f / sum0, inv1 = 1.f / sum1;
#pragma unroll
    for (int nt = 0; nt < 8; ++nt) {
        sacc[nt][0] *= inv0; sacc[nt][1] *= inv0;
        sacc[nt][2] *= inv1; sacc[nt][3] *= inv1;
    }

    float oacc[4][4];
#pragma unroll
    for (int nt = 0; nt < 4; ++nt)
#pragma unroll
        for (int qq = 0; qq < 4; ++qq) oacc[nt][qq] = 0.f;

#pragma unroll
    for (int s = 0; s < 4; ++s) {
        uint32_t ah[4];
#pragma unroll
        for (int half = 0; half < 2; ++half) {
            float* t = sacc[2*s + half];
            __half2 p0 = make_half2(__float2half_rn(t[0]), __float2half_rn(t[1]));
            __half2 p1 = make_half2(__float2half_rn(t[2]), __float2half_rn(t[3]));
            ah[half*2]     = *(uint32_t*)&p0;
            ah[half*2 + 1] = *(uint32_t*)&p1;
        }
#pragma unroll
        for (int half = 0; half < 2; ++half) {
            uint32_t t[4];
            ldsm4t(t, sb + AV + sw64(s * 16 + aro, half * 2 + cgs));
            uint32_t b0[2] = {t[0], t[1]}, b1[2] = {t[2], t[3]};
            mma_f16(oacc[half*2],   ah, b0);
            mma_f16(oacc[half*2+1], ah, b1);
        }
    }

#pragma unroll
    for (int nt = 0; nt < 4; ++nt) {
        int e0 = h * 32 + nt * 8 + jc;
        size_t o0 = ((size_t)win * D + i0) * C + e0;
        size_t o1 = ((size_t)win * D + i1) * C + e0;
        __half2 p0 = make_half2(__float2half_rn(oacc[nt][0]), __float2half_rn(oacc[nt][1]));
        __half2 p1 = make_half2(__float2half_rn(oacc[nt][2]), __float2half_rn(oacc[nt][3]));
        *(uint32_t*)&g_ctx[o0] = *(uint32_t*)&p0;
        *(uint32_t*)&g_ctx[o1] = *(uint32_t*)&p1;
    }
}

// ---------------------------------------------------------------------------
// Kernel 3: projection + window-reverse/roll scatter. grid = (3, 512).
// ---------------------------------------------------------------------------
__global__ __launch_bounds__(512, 1) void proj_mma(
    const float* __restrict__ bias, float* __restrict__ out)
{
    extern __shared__ char smem[];
    const uint32_t sb = smem_u32(smem);
    const int tid = threadIdx.x, lane = tid & 31, wid = tid >> 5;
    const int wquad = blockIdx.y;
    const int n0 = blockIdx.x * 128;
    const int wm = (wid & 3) * 64, wn = (wid >> 2) * 32;

    const int arow = tid >> 1;
    const int cgA0 = (tid & 1) * 2;
    const uint32_t dA0 = sw64(arow, cgA0), dA1 = sw64(arow, cgA0 + 1);
    const int brow = tid >> 2;
    const int cgB  = tid & 3;
    const uint32_t dB = sw64(brow, cgB);

    const __half* pA0 = g_ctx + ((size_t)wquad * 256 + arow) * C + cgA0 * 8;
    const __half* pA1 = pA0 + 8;
    const __half* pB  = g_wout + (size_t)(n0 + brow) * C + cgB * 8;

    float acc[4][4][4];
#pragma unroll
    for (int mi = 0; mi < 4; ++mi)
#pragma unroll
        for (int ni = 0; ni < 4; ++ni)
#pragma unroll
            for (int q = 0; q < 4; ++q) acc[mi][ni][q] = 0.f;

    issue_chunk(sb,                0,   dA0, dA1, dB, pA0, pA1, pB);
    issue_chunk(sb + STAGE_STRIDE, KCH, dA0, dA1, dB, pA0, pA1, pB);

#pragma unroll 1
    for (int it = 0; it < NCHUNK; ++it) {
        if (it + 2 < NCHUNK)
            issue_chunk(sb + ((it + 2) % NSTAGE) * STAGE_STRIDE, (it + 2) * KCH,
                        dA0, dA1, dB, pA0, pA1, pB);
        if (it < NCHUNK - 2)      { CP_WAIT2(); }
        else if (it == NCHUNK - 2){ CP_WAIT1(); }
        else                      { CP_WAIT0(); }
        __syncthreads();
        mma_stage(sb + (it % NSTAGE) * STAGE_STRIDE, lane, wm, wn, acc);
        __syncthreads();
    }

    float (*S)[132] = (float(*)[132])smem;
    acc_to_smem(S, tid, acc);
    __syncthreads();

    const float4 bb = *(const float4*)&bias[n0 + lane * 4];
#pragma unroll
    for (int p = 0; p < 16; ++p) {
        int r = p * 16 + wid;
        float4 v = *(const float4*)&S[r][lane * 4];
        v.x += bb.x; v.y += bb.y; v.z += bb.z; v.w += bb.w;
        int tk = wquad * 256 + r;
        int win = tk >> 6;
        int img = win >> 6, wi = win & 63, wr = wi >> 3, wc = wi & 7;
        int t = tk & 63, ri = t >> 3, ci = t & 7;
        int gr = (wr * 8 + ri + 4) & 63;   // window-reverse + roll(+4) == +4 mod 64
        int gc = (wc * 8 + ci + 4) & 63;
        *(float4*)(out + (((size_t)img * 64 + gr) * 64 + gc) * C + n0 + lane * 4) = v;
    }
}

// ---------------------------------------------------------------------------
namespace {
struct ForceLoad {
    ForceLoad() {
        void* p = nullptr;
        cudaGetSymbolAddress(&p, g_qkv);
        cudaGetSymbolAddress(&p, g_ctx);
        cudaFuncSetAttribute(qkv_mma,  cudaFuncAttributeMaxDynamicSharedMemorySize, SMEM_BYTES);
        cudaFuncSetAttribute(proj_mma, cudaFuncAttributeMaxDynamicSharedMemorySize, SMEM_BYTES);
    }
};
ForceLoad g_force_load;
}

extern "C" void kernel_launch(void* const* d_in, const int* in_sizes, int n_in,
                              void* d_out, int out_size)
{
    (void)in_sizes; (void)n_in; (void)out_size;
    const float* x      = (const float*)d_in[0];
    const float* w_qkv  = (const float*)d_in[1];
    const float* b_qkv  = (const float*)d_in[2];
    const float* w_out  = (const float*)d_in[3];
    const float* b_out  = (const float*)d_in[4];
    const float* btab   = (const float*)d_in[5];
    float* out = (float*)d_out;

    prep_x   <<<49152, 256>>>(x);
    prep_wqkv<<<432, 256>>>(w_qkv);
    prep_wout<<<144, 256>>>(w_out);
    qkv_mma  <<<dim3(9, NWIN / 4), 512, SMEM_BYTES>>>(b_qkv);
    attn_mma <<<dim3(NWIN, 3), 512>>>(btab);
    proj_mma <<<dim3(3, NWIN / 4), 512, SMEM_BYTES>>>(b_out, out);
}

// round 13
// speedup vs baseline: 1.0629x; 1.0629x over previous
#include <cuda_runtime.h>
#include <cuda_fp16.h>
#include <cstdint>

#define C        384
#define NQKV     1152
#define NWIN     2048   // 32 images * 64 windows
#define D        64     // tokens per window
#define KCH      32     // K per pipeline chunk
#define NCHUNK   (C / KCH)   // 12
#define NSTAGE   3

// GEMM stage layout (fp16): A[128][32] (8KB) + B[128][32] (8KB)
#define SA    0
#define SB    8192
#define STAGE_STRIDE 16384
#define SMEM_BYTES 67584           // epilogue S[128][132]*4 = 67584 > 3*16384

// ---------------------------------------------------------------------------
// Scratch (device globals are the sanctioned scratch mechanism).
__device__ __half g_x_h [(size_t)32 * 64 * 64 * C];   // fp16 activations
__device__ __half g_qkv [(size_t)NWIN * D * NQKV];    // fp16 qkv
__device__ __half g_ctx [(size_t)NWIN * D * C];       // fp16 attn output
__device__ __half g_wqkv[(size_t)NQKV * C];           // W^T [n][k] fp16
__device__ __half g_wout[(size_t)C * C];

// ---------------------------------------------------------------------------
__device__ __forceinline__ uint32_t smem_u32(const void* p) {
    uint32_t a;
    asm("{ .reg .u64 t; cvta.to.shared.u64 t, %1; cvt.u32.u64 %0, t; }"
        : "=r"(a) : "l"(p));
    return a;
}
__device__ __forceinline__ void cp16(uint32_t d, const void* s) {
    asm volatile("cp.async.ca.shared.global [%0], [%1], 16;" :: "r"(d), "l"(s));
}
#define CP_COMMIT() asm volatile("cp.async.commit_group;" ::: "memory")
#define CP_WAIT0()  asm volatile("cp.async.wait_group 0;" ::: "memory")
#define CP_WAIT1()  asm volatile("cp.async.wait_group 1;" ::: "memory")
#define CP_WAIT2()  asm volatile("cp.async.wait_group 2;" ::: "memory")

__device__ __forceinline__ void ldsm4(uint32_t r[4], uint32_t addr) {
    asm volatile("ldmatrix.sync.aligned.m8n8.x4.shared.b16 {%0,%1,%2,%3}, [%4];"
                 : "=r"(r[0]), "=r"(r[1]), "=r"(r[2]), "=r"(r[3]) : "r"(addr));
}
__device__ __forceinline__ void ldsm4t(uint32_t r[4], uint32_t addr) {
    asm volatile("ldmatrix.sync.aligned.m8n8.x4.trans.shared.b16 {%0,%1,%2,%3}, [%4];"
                 : "=r"(r[0]), "=r"(r[1]), "=r"(r[2]), "=r"(r[3]) : "r"(addr));
}
__device__ __forceinline__ void mma_f16(float d[4], const uint32_t a[4],
                                        const uint32_t b[2]) {
    asm volatile(
        "mma.sync.aligned.m16n8k16.row.col.f32.f16.f16.f32 "
        "{%0,%1,%2,%3}, {%4,%5,%6,%7}, {%8,%9}, {%0,%1,%2,%3};"
        : "+f"(d[0]), "+f"(d[1]), "+f"(d[2]), "+f"(d[3])
        : "r"(a[0]), "r"(a[1]), "r"(a[2]), "r"(a[3]), "r"(b[0]), "r"(b[1]));
}
// 64-byte-row swizzle: granule col ^= (row>>1)&3  (conflict-free for ldsm/STS/cp)
__device__ __forceinline__ uint32_t sw64(int row, int cg) {
    return (uint32_t)(row * 64 + ((cg ^ ((row >> 1) & 3)) << 4));
}

// ---------------------------------------------------------------------------
// Prep kernels: fp16 conversion (+ transpose for weights).
// ---------------------------------------------------------------------------
__global__ void prep_x(const float* __restrict__ x) {
    size_t i4 = ((size_t)blockIdx.x * 256 + threadIdx.x) * 4;
    float4 v = *(const float4*)(x + i4);
    __half2 a = make_half2(__float2half_rn(v.x), __float2half_rn(v.y));
    __half2 b = make_half2(__float2half_rn(v.z), __float2half_rn(v.w));
    *(uint2*)&g_x_h[i4] = make_uint2(*(uint32_t*)&a, *(uint32_t*)&b);
}
__global__ void prep_wqkv(const float* __restrict__ w) {
    int lin = blockIdx.x * 256 + threadIdx.x;
    int k4 = (lin % 96) * 4;
    int n  = lin / 96;
    __half2 a = make_half2(__float2half_rn(w[(size_t)(k4 + 0) * NQKV + n]),
                           __float2half_rn(w[(size_t)(k4 + 1) * NQKV + n]));
    __half2 b = make_half2(__float2half_rn(w[(size_t)(k4 + 2) * NQKV + n]),
                           __float2half_rn(w[(size_t)(k4 + 3) * NQKV + n]));
    *(uint2*)&g_wqkv[(size_t)n * C + k4] = make_uint2(*(uint32_t*)&a, *(uint32_t*)&b);
}
__global__ void prep_wout(const float* __restrict__ w) {
    int lin = blockIdx.x * 256 + threadIdx.x;
    int k4 = (lin % 96) * 4;
    int n  = lin / 96;
    __half2 a = make_half2(__float2half_rn(w[(size_t)(k4 + 0) * C + n]),
                           __float2half_rn(w[(size_t)(k4 + 1) * C + n]));
    __half2 b = make_half2(__float2half_rn(w[(size_t)(k4 + 2) * C + n]),
                           __float2half_rn(w[(size_t)(k4 + 3) * C + n]));
    *(uint2*)&g_wout[(size_t)n * C + k4] = make_uint2(*(uint32_t*)&a, *(uint32_t*)&b);
}

// Gathered token index (roll -4 + window partition); row 0..127 of a 2-window CTA.
__device__ __forceinline__ size_t qkv_row_off(int wpair, int row) {
    int win = wpair * 2 + (row >> 6);
    int img = win >> 6, wi = win & 63, wr = wi >> 3, wc = wi & 7;
    int t = row & 63, ri = t >> 3, ci = t & 7;
    int gr = (wr * 8 + ri + 4) & 63;
    int gc = (wc * 8 + ci + 4) & 63;
    return (((size_t)img * 64 + gr) * 64 + gc) * C;
}

// ---------------------------------------------------------------------------
// mma on one staged chunk (KCH=32): fp16 single pass. 8 warps, 128x128 acc.
// Warp layout: wm = (wid&1)*64, wn = (wid>>1)*32.
// ---------------------------------------------------------------------------
__device__ __forceinline__ void mma_stage(uint32_t sbase, int lane, int wm, int wn,
                                          float acc[4][4][4])
{
    const int aro = (lane & 7) + ((lane >> 3) & 1) * 8;
    const int cgs = lane >> 4;
#pragma unroll
    for (int ks = 0; ks < 2; ++ks) {
        const int cg = ks * 2 + cgs;
        uint32_t bh[4][2];
#pragma unroll
        for (int np = 0; np < 2; ++np) {
            int r = wn + np * 16 + aro;
            uint32_t t[4];
            ldsm4(t, sbase + SB + sw64(r, cg));
            bh[np*2][0] = t[0]; bh[np*2+1][0] = t[1];
            bh[np*2][1] = t[2]; bh[np*2+1][1] = t[3];
        }
        uint32_t a[4][4];
#pragma unroll
        for (int mi = 0; mi < 4; ++mi)
            ldsm4(a[mi], sbase + SA + sw64(wm + mi * 16 + aro, cg));
#pragma unroll
        for (int mi = 0; mi < 4; ++mi)
#pragma unroll
            for (int ni = 0; ni < 4; ++ni)
                mma_f16(acc[mi][ni], a[mi], bh[ni]);
    }
}

__device__ __forceinline__ void acc_to_smem(float (*S)[132], int tid,
                                            float acc[4][4][4])
{
    const int lane = tid & 31, wid = tid >> 5;
    const int wm = (wid & 1) * 64;
    const int wn = (wid >> 1) * 32;
    const int er = lane >> 2, ec = (lane & 3) * 2;
#pragma unroll
    for (int mi = 0; mi < 4; ++mi)
#pragma unroll
        for (int ni = 0; ni < 4; ++ni) {
            float* d = acc[mi][ni];
            *(float2*)&S[wm + mi*16 + er][wn + ni*8 + ec]     = make_float2(d[0], d[1]);
            *(float2*)&S[wm + mi*16 + 8 + er][wn + ni*8 + ec] = make_float2(d[2], d[3]);
        }
}

// Issue one chunk: per thread 2 A granules + 2 B granules.
__device__ __forceinline__ void issue_chunk(
    uint32_t s0, int k0,
    uint32_t dA0, uint32_t dA1,
    const __half* pA0, const __half* pA1, const __half* pB0, const __half* pB1)
{
    cp16(s0 + SA + dA0, pA0 + k0);
    cp16(s0 + SA + dA1, pA1 + k0);
    cp16(s0 + SB + dA0, pB0 + k0);
    cp16(s0 + SB + dA1, pB1 + k0);
    CP_COMMIT();
}

// ---------------------------------------------------------------------------
// Kernel 1: QKV. grid = (9, 1024), 256 threads, 2 CTAs/SM. Writes g_qkv fp16.
// ---------------------------------------------------------------------------
__global__ __launch_bounds__(256, 2) void qkv_mma(const float* __restrict__ bias)
{
    extern __shared__ char smem[];
    const uint32_t sb = smem_u32(smem);
    const int tid = threadIdx.x, lane = tid & 31, wid = tid >> 5;
    const int wpair = blockIdx.y;
    const int n0 = blockIdx.x * 128;
    const int wm = (wid & 1) * 64, wn = (wid >> 1) * 32;

    // cp map: row = tid>>1 (0..127), granules (tid&1)*2 and +1 (for both A and B)
    const int row = tid >> 1;
    const int cg0 = (tid & 1) * 2;
    const uint32_t dA0 = sw64(row, cg0), dA1 = sw64(row, cg0 + 1);

    const __half* pA0 = g_x_h + qkv_row_off(wpair, row) + cg0 * 8;
    const __half* pA1 = pA0 + 8;
    const __half* pB0 = g_wqkv + (size_t)(n0 + row) * C + cg0 * 8;
    const __half* pB1 = pB0 + 8;

    float acc[4][4][4];
#pragma unroll
    for (int mi = 0; mi < 4; ++mi)
#pragma unroll
        for (int ni = 0; ni < 4; ++ni)
#pragma unroll
            for (int q = 0; q < 4; ++q) acc[mi][ni][q] = 0.f;

    issue_chunk(sb,                0,   dA0, dA1, pA0, pA1, pB0, pB1);
    issue_chunk(sb + STAGE_STRIDE, KCH, dA0, dA1, pA0, pA1, pB0, pB1);

#pragma unroll 1
    for (int it = 0; it < NCHUNK; ++it) {
        if (it + 2 < NCHUNK)
            issue_chunk(sb + ((it + 2) % NSTAGE) * STAGE_STRIDE, (it + 2) * KCH,
                        dA0, dA1, pA0, pA1, pB0, pB1);
        if (it < NCHUNK - 2)      { CP_WAIT2(); }
        else if (it == NCHUNK - 2){ CP_WAIT1(); }
        else                      { CP_WAIT0(); }
        __syncthreads();
        mma_stage(sb + (it % NSTAGE) * STAGE_STRIDE, lane, wm, wn, acc);
        __syncthreads();
    }

    float (*S)[132] = (float(*)[132])smem;
    acc_to_smem(S, tid, acc);
    __syncthreads();

    const float4 bb = *(const float4*)&bias[n0 + lane * 4];
#pragma unroll
    for (int p = 0; p < 16; ++p) {
        int r = p * 8 + wid;
        float4 v = *(const float4*)&S[r][lane * 4];
        __half2 h0 = make_half2(__float2half_rn(v.x + bb.x), __float2half_rn(v.y + bb.y));
        __half2 h1 = make_half2(__float2half_rn(v.z + bb.z), __float2half_rn(v.w + bb.w));
        size_t m = (size_t)wpair * 128 + r;
        *(uint2*)&g_qkv[m * NQKV + n0 + lane * 4] =
            make_uint2(*(uint32_t*)&h0, *(uint32_t*)&h1);
    }
}

// ---------------------------------------------------------------------------
// Kernel 2: flash-style fp16 HMMA attention (R10 version). grid = (2048, 12).
// ---------------------------------------------------------------------------
#define AQ 0
#define AK 4096
#define AV 8192

__global__ __launch_bounds__(128) void attn_mma(const float* __restrict__ bt)
{
    __shared__ char ts[12288];
    __shared__ float s_bias[32];
    const uint32_t sb = smem_u32(ts);
    const int tid = threadIdx.x, lane = tid & 31, w = tid >> 5;
    const int win = blockIdx.x, h = blockIdx.y;
    const float scale = 0.17677669529663687f;  // 1/sqrt(32)

    if (tid < 29) s_bias[tid] = bt[(tid + 15) * 12 + h];

    {
        const int row = tid >> 1;
        const int cg0 = (tid & 1) * 2;
        const uint32_t d0 = sw64(row, cg0), d1 = sw64(row, cg0 + 1);
        size_t base = ((size_t)win * D + row) * NQKV + (size_t)h * 32 + cg0 * 8;
        const __half* p = g_qkv + base;
        cp16(sb + AQ + d0, p);        cp16(sb + AQ + d1, p + 8);
        cp16(sb + AK + d0, p + 384);  cp16(sb + AK + d1, p + 392);
        cp16(sb + AV + d0, p + 768);  cp16(sb + AV + d1, p + 776);
        CP_COMMIT();
    }
    CP_WAIT0();
    __syncthreads();

    const int aro = (lane & 7) + ((lane >> 3) & 1) * 8;
    const int cgs = lane >> 4;

    uint32_t q[2][4];
#pragma unroll
    for (int ks = 0; ks < 2; ++ks)
        ldsm4(q[ks], sb + AQ + sw64(w * 16 + aro, ks * 2 + cgs));

    float sacc[8][4];
#pragma unroll
    for (int nt = 0; nt < 8; ++nt)
#pragma unroll
        for (int qq = 0; qq < 4; ++qq) sacc[nt][qq] = 0.f;

#pragma unroll
    for (int jb = 0; jb < 4; ++jb) {
#pragma unroll
        for (int ks = 0; ks < 2; ++ks) {
            uint32_t t[4];
            ldsm4(t, sb + AK + sw64(jb * 16 + aro, ks * 2 + cgs));
            uint32_t b0[2] = {t[0], t[2]}, b1[2] = {t[1], t[3]};
            mma_f16(sacc[jb*2],   q[ks], b0);
            mma_f16(sacc[jb*2+1], q[ks], b1);
        }
    }

    const int i0 = w * 16 + (lane >> 2);
    const int i1 = i0 + 8;
    const int jc = 2 * (lane & 3);
    const int wr8 = ((win & 63) >> 3) * 8, wc8 = (win & 7) * 8;
#define SUMOF(t)  (((t) >> 3) + ((t) & 7))
#define REGOF(t)  ({ int _gr = wr8 + ((t) >> 3), _gc = wc8 + ((t) & 7); \
                     (_gr < 56 ? 0 : (_gr < 60 ? 1 : 2)) * 3 + \
                     (_gc < 56 ? 0 : (_gc < 60 ? 1 : 2)); })
    const int isum0 = SUMOF(i0), ireg0 = REGOF(i0);
    const int isum1 = SUMOF(i1), ireg1 = REGOF(i1);

    float mx0 = -1e30f, mx1 = -1e30f;
#pragma unroll
    for (int nt = 0; nt < 8; ++nt) {
        int j0 = nt * 8 + jc, j1 = j0 + 1;
        int jsum0 = SUMOF(j0), jreg0 = REGOF(j0);
        int jsum1 = jsum0 + 1,  jreg1 = REGOF(j1);
        float s0 = sacc[nt][0] * scale + s_bias[isum0 - jsum0 + 14] + (ireg0 == jreg0 ? 0.f : -100.f);
        float s1 = sacc[nt][1] * scale + s_bias[isum0 - jsum1 + 14] + (ireg0 == jreg1 ? 0.f : -100.f);
        float s2 = sacc[nt][2] * scale + s_bias[isum1 - jsum0 + 14] + (ireg1 == jreg0 ? 0.f : -100.f);
        float s3 = sacc[nt][3] * scale + s_bias[isum1 - jsum1 + 14] + (ireg1 == jreg1 ? 0.f : -100.f);
        sacc[nt][0] = s0; sacc[nt][1] = s1; sacc[nt][2] = s2; sacc[nt][3] = s3;
        mx0 = fmaxf(mx0, fmaxf(s0, s1));
        mx1 = fmaxf(mx1, fmaxf(s2, s3));
    }
    mx0 = fmaxf(mx0, __shfl_xor_sync(0xffffffffu, mx0, 1));
    mx0 = fmaxf(mx0, __shfl_xor_sync(0xffffffffu, mx0, 2));
    mx1 = fmaxf(mx1, __shfl_xor_sync(0xffffffffu, mx1, 1));
    mx1 = fmaxf(mx1, __shfl_xor_sync(0xffffffffu, mx1, 2));

    float sum0 = 0.f, sum1 = 0.f;
#pragma unroll
    for (int nt = 0; nt < 8; ++nt) {
        float e0 = __expf(sacc[nt][0] - mx0);
        float e1 = __expf(sacc[nt][1] - mx0);
        float e2 = __expf(sacc[nt][2] - mx1);
        float e3 = __expf(sacc[nt][3] - mx1);
        sacc[nt][0] = e0; sacc[nt][1] = e1; sacc[nt][2] = e2; sacc[nt][3] = e3;
        sum0 += e0 + e1; sum1 += e2 + e3;
    }
    sum0 += __shfl_xor_sync(0xffffffffu, sum0, 1);
    sum0 += __shfl_xor_sync(0xffffffffu, sum0, 2);
    sum1 += __shfl_xor_sync(0xffffffffu, sum1, 1);
    sum1 += __shfl_xor_sync(0xffffffffu, sum1, 2);
    float inv0 = 1.f / sum0, inv1 = 1.f / sum1;
#pragma unroll
    for (int nt = 0; nt < 8; ++nt) {
        sacc[nt][0] *= inv0; sacc[nt][1] *= inv0;
        sacc[nt][2] *= inv1; sacc[nt][3] *= inv1;
    }

    float oacc[4][4];
#pragma unroll
    for (int nt = 0; nt < 4; ++nt)
#pragma unroll
        for (int qq = 0; qq < 4; ++qq) oacc[nt][qq] = 0.f;

#pragma unroll
    for (int s = 0; s < 4; ++s) {
        uint32_t ah[4];
#pragma unroll
        for (int half = 0; half < 2; ++half) {
            float* t = sacc[2*s + half];
            __half2 p0 = make_half2(__float2half_rn(t[0]), __float2half_rn(t[1]));
            __half2 p1 = make_half2(__float2half_rn(t[2]), __float2half_rn(t[3]));
            ah[half*2]     = *(uint32_t*)&p0;
            ah[half*2 + 1] = *(uint32_t*)&p1;
        }
#pragma unroll
        for (int half = 0; half < 2; ++half) {
            uint32_t t[4];
            ldsm4t(t, sb + AV + sw64(s * 16 + aro, half * 2 + cgs));
            uint32_t b0[2] = {t[0], t[1]}, b1[2] = {t[2], t[3]};
            mma_f16(oacc[half*2],   ah, b0);
            mma_f16(oacc[half*2+1], ah, b1);
        }
    }

#pragma unroll
    for (int nt = 0; nt < 4; ++nt) {
        int e0 = h * 32 + nt * 8 + jc;
        size_t o0 = ((size_t)win * D + i0) * C + e0;
        size_t o1 = ((size_t)win * D + i1) * C + e0;
        __half2 p0 = make_half2(__float2half_rn(oacc[nt][0]), __float2half_rn(oacc[nt][1]));
        __half2 p1 = make_half2(__float2half_rn(oacc[nt][2]), __float2half_rn(oacc[nt][3]));
        *(uint32_t*)&g_ctx[o0] = *(uint32_t*)&p0;
        *(uint32_t*)&g_ctx[o1] = *(uint32_t*)&p1;
    }
}

// ---------------------------------------------------------------------------
// Kernel 3: projection + window-reverse/roll scatter. grid = (3, 1024), 256 thr.
// ---------------------------------------------------------------------------
__global__ __launch_bounds__(256, 2) void proj_mma(
    const float* __restrict__ bias, float* __restrict__ out)
{
    extern __shared__ char smem[];
    const uint32_t sb = smem_u32(smem);
    const int tid = threadIdx.x, lane = tid & 31, wid = tid >> 5;
    const int wpair = blockIdx.y;
    const int n0 = blockIdx.x * 128;
    const int wm = (wid & 1) * 64, wn = (wid >> 1) * 32;

    const int row = tid >> 1;
    const int cg0 = (tid & 1) * 2;
    const uint32_t dA0 = sw64(row, cg0), dA1 = sw64(row, cg0 + 1);

    const __half* pA0 = g_ctx + ((size_t)wpair * 128 + row) * C + cg0 * 8;
    const __half* pA1 = pA0 + 8;
    const __half* pB0 = g_wout + (size_t)(n0 + row) * C + cg0 * 8;
    const __half* pB1 = pB0 + 8;

    float acc[4][4][4];
#pragma unroll
    for (int mi = 0; mi < 4; ++mi)
#pragma unroll
        for (int ni = 0; ni < 4; ++ni)
#pragma unroll
            for (int q = 0; q < 4; ++q) acc[mi][ni][q] = 0.f;

    issue_chunk(sb,                0,   dA0, dA1, pA0, pA1, pB0, pB1);
    issue_chunk(sb + STAGE_STRIDE, KCH, dA0, dA1, pA0, pA1, pB0, pB1);

#pragma unroll 1
    for (int it = 0; it < NCHUNK; ++it) {
        if (it + 2 < NCHUNK)
            issue_chunk(sb + ((it + 2) % NSTAGE) * STAGE_STRIDE, (it + 2) * KCH,
                        dA0, dA1, pA0, pA1, pB0, pB1);
        if (it < NCHUNK - 2)      { CP_WAIT2(); }
        else if (it == NCHUNK - 2){ CP_WAIT1(); }
        else                      { CP_WAIT0(); }
        __syncthreads();
        mma_stage(sb + (it % NSTAGE) * STAGE_STRIDE, lane, wm, wn, acc);
        __syncthreads();
    }

    float (*S)[132] = (float(*)[132])smem;
    acc_to_smem(S, tid, acc);
    __syncthreads();

    const float4 bb = *(const float4*)&bias[n0 + lane * 4];
#pragma unroll
    for (int p = 0; p < 16; ++p) {
        int r = p * 8 + wid;
        float4 v = *(const float4*)&S[r][lane * 4];
        v.x += bb.x; v.y += bb.y; v.z += bb.z; v.w += bb.w;
        int tk = wpair * 128 + r;
        int win = tk >> 6;
        int img = win >> 6, wi = win & 63, wr = wi >> 3, wc = wi & 7;
        int t = tk & 63, ri = t >> 3, ci = t & 7;
        int gr = (wr * 8 + ri + 4) & 63;   // window-reverse + roll(+4) == +4 mod 64
        int gc = (wc * 8 + ci + 4) & 63;
        *(float4*)(out + (((size_t)img * 64 + gr) * 64 + gc) * C + n0 + lane * 4) = v;
    }
}

// ---------------------------------------------------------------------------
namespace {
struct ForceLoad {
    ForceLoad() {
        void* p = nullptr;
        cudaGetSymbolAddress(&p, g_qkv);
        cudaGetSymbolAddress(&p, g_ctx);
        cudaFuncSetAttribute(qkv_mma,  cudaFuncAttributeMaxDynamicSharedMemorySize, SMEM_BYTES);
        cudaFuncSetAttribute(proj_mma, cudaFuncAttributeMaxDynamicSharedMemorySize, SMEM_BYTES);
    }
};
ForceLoad g_force_load;
}

extern "C" void kernel_launch(void* const* d_in, const int* in_sizes, int n_in,
                              void* d_out, int out_size)
{
    (void)in_sizes; (void)n_in; (void)out_size;
    const float* x      = (const float*)d_in[0];
    const float* w_qkv  = (const float*)d_in[1];
    const float* b_qkv  = (const float*)d_in[2];
    const float* w_out  = (const float*)d_in[3];
    const float* b_out  = (const float*)d_in[4];
    const float* btab   = (const float*)d_in[5];
    float* out = (float*)d_out;

    prep_x   <<<49152, 256>>>(x);
    prep_wqkv<<<432, 256>>>(w_qkv);
    prep_wout<<<144, 256>>>(w_out);
    qkv_mma  <<<dim3(9, NWIN / 2), 256, SMEM_BYTES>>>(b_qkv);
    attn_mma <<<dim3(NWIN, 12), 128>>>(btab);
    proj_mma <<<dim3(3, NWIN / 2), 256, SMEM_BYTES>>>(b_out, out);
}